// round 2
// baseline (speedup 1.0000x reference)
#include <cuda_runtime.h>

__global__ void quantum_probs_kernel(const float4* __restrict__ in,
                                     float4* __restrict__ out,
                                     int n) {
    int i = blockIdx.x * blockDim.x + threadIdx.x;
    if (i < n) {
        float4 row = in[i];           // coalesced 16B load; only .x needed but full line is fetched anyway
        float half = row.x * 0.5f;
        float s, c;
        __sincosf(half, &s, &c);
        float c2 = c * c;
        float s2 = s * s;
        out[i] = make_float4(c2 * c2, c2 * s2, s2 * s2, s2 * c2);
    }
}

extern "C" void kernel_launch(void* const* d_in, const int* in_sizes, int n_in,
                              void* d_out, int out_size) {
    const float4* in = (const float4*)d_in[0];
    float4* out = (float4*)d_out;
    int n = in_sizes[0] / 4;          // N rows (in_sizes is element count = N*4)
    int threads = 256;
    int blocks = (n + threads - 1) / threads;
    quantum_probs_kernel<<<blocks, threads>>>(in, out, n);
}